// round 16
// baseline (speedup 1.0000x reference)
#include <cuda_runtime.h>
#include <math.h>

#define FULLMASK 0xFFFFFFFFu

// ---------------------------------------------------------------------------
// Focal_loss2 — fused focal loss, single launch, barrier-free z-march.
// R15 base (ZC=16, 577 blocks, 4 blk/SM, full unroll) + early prob issue:
// hit requires cen >= pmm and cen >= pmc, both known at iteration START, so
// the prob load is issued before the new plane's shuffle/max chain resolves
// (full-iteration latency cover) and the final mask needs only one compare.
// Output f32[38]: [loss_pos, loss_neg, count_pos, count_neg, wsum_pos,
//                  wsum_neg, pred_prob_min[2,2,8]]
// ---------------------------------------------------------------------------

constexpr int ZC = 16;                    // z-march chunk
constexpr int A_YT = 16, A_ZT = 8;        // D=128: 8 rows/block (warp/row)
constexpr int B_YT = 4,  B_ZT = 4;        // D=64 : 16 rows/block (half-warp/row)
constexpr int NBLK_A = A_YT * A_ZT * 4;   // 512
constexpr int NBLK_B = B_YT * B_ZT * 4;   // 64
constexpr int NBLK   = NBLK_A + NBLK_B;   // 576 neg blocks (+1 pos block)

// Cross-block state (no allocation allowed -> __device__ globals).
__device__ float2   g_part[NBLK];   // neg per-block partials {sum(w*nll), sum(w)}
__device__ double   g_posv[4];      // {loss0, w0, loss1, w1}
__device__ int      g_segres[32];   // segment-min results (int-ordered floats)
__device__ unsigned g_done;         // completion ticket; reset by finalize

__device__ __forceinline__ float4 f4max(float4 a, float4 b) {
    return make_float4(fmaxf(a.x, b.x), fmaxf(a.y, b.y),
                       fmaxf(a.z, b.z), fmaxf(a.w, b.w));
}

// ---------------------------------------------------------------------------
// Negative branch, warp-autonomous: each group of LPG lanes owns one output
// row y and marches z. Out-of-range rows/planes are CLAMPED to the center
// row/plane (max unchanged — center already in window == SAME padding).
// ---------------------------------------------------------------------------
template<int D, int YT, int ZT>
__device__ __forceinline__ void neg_impl(const float* __restrict__ L,
                                         const float* __restrict__ P,
                                         int bid, int gbid, float* sred)
{
    constexpr int LPG = D / 4;        // lanes per row-group (32 for a, 16 for b)
    constexpr int GPB = 256 / LPG;    // rows per block (8 for a, 16 for b)
    constexpr int PL  = D * D;        // floats per z-plane

    const int ytile = bid % YT;
    const int zc    = (bid / YT) % ZT;
    const int ba    = bid / (YT * ZT);

    const int tid = threadIdx.x;
    const int g   = tid / LPG;        // row index in block
    const int xl  = tid % LPG;        // x lane within group
    const int x   = xl * 4;
    const int y   = ytile * GPB + g;  // 0..D-1
    const int z0  = zc * ZC;

    const size_t vol = (size_t)D * PL;
    const float* Lb = L + (size_t)ba * vol;
    const float* Pb = P + (size_t)ba * vol;

    // bases at plane z0 so unrolled-loop offsets are compile-time constants
    const float* pc0 = Lb + (size_t)z0 * PL + (size_t)y * D + x;
    const float* pm0 = (y > 0)     ? pc0 - D : pc0;       // clamped neighbors
    const float* pp0 = (y < D - 1) ? pc0 + D : pc0;
    const float* pq0 = Pb + (size_t)z0 * PL + (size_t)y * D + x;

    auto ld3 = [&](int rel, float4& r0, float4& r1, float4& r2) {
        const long long o = (long long)rel * PL;
        r1 = *reinterpret_cast<const float4*>(pc0 + o);
        r0 = *reinterpret_cast<const float4*>(pm0 + o);
        r2 = *reinterpret_cast<const float4*>(pp0 + o);
    };

    // horizontal 3-max across the 4 components + lane neighbors (via shuffle).
    auto xmax3 = [&](float4 v) -> float4 {
        float lft = __shfl_up_sync(FULLMASK, v.w, 1);
        float rgt = __shfl_down_sync(FULLMASK, v.x, 1);
        if (xl == 0)       lft = -INFINITY;   // x edge (isolates half-warp groups too)
        if (xl == LPG - 1) rgt = -INFINITY;
        float4 m;
        m.x = fmaxf(lft,  fmaxf(v.x, v.y));
        m.y = fmaxf(v.x,  fmaxf(v.y, v.z));
        m.z = fmaxf(v.y,  fmaxf(v.z, v.w));
        m.w = fmaxf(rgt,  fmaxf(v.z, v.w));
        return m;
    };

    // ---- prologue: pm(z0-1 clamped), pm(z0); plane z0+1 loads in flight
    float4 a0, a1, a2, b0, b1, b2;
    ld3(z0 > 0 ? -1 : 0, a0, a1, a2);
    float4 pmm = xmax3(f4max(a0, f4max(a1, a2)));     // pm(z0-1)
    ld3(0, a0, a1, a2);
    float4 cen = a1;                                   // raw center @ z0
    float4 pmc = xmax3(f4max(a0, f4max(a1, a2)));     // pm(z0)
    ld3(1, b0, b1, b2);                                // z0+1 <= D-1 always

    float s_lw = 0.f, s_w = 0.f;
    const int relmax = (D - 1) - z0;                   // clamp bound in rel coords

    // one z-step: consume plane z0+i+1 (in b*), prefetch plane rel rn.
    // Early prob issue: cen==27-max  <=>  cen>=pmm & cen>=pmc & cen>=pm_next;
    // the first two are known NOW, before the new plane's chain resolves.
    auto step = [&](int i, int rn) {
        const float4 c0 = b0, c1 = b1, c2 = b2;
        ld3(rn, b0, b1, b2);                           // plane loads first
        const float4 emx = f4max(pmm, pmc);
        const unsigned em = (unsigned)(cen.x >= emx.x)
                          | ((unsigned)(cen.y >= emx.y) << 1)
                          | ((unsigned)(cen.z >= emx.z) << 2)
                          | ((unsigned)(cen.w >= emx.w) << 3);
        float4 pg;
        if (em)                                        // ~20% of lanes; covered by
            pg = __ldcs(reinterpret_cast<const float4*>(   // the chain below
                            pq0 + (long long)i * PL));
        const float4 pm_next = xmax3(f4max(c0, f4max(c1, c2)));
        const unsigned nm = em & ( (unsigned)(cen.x >= pm_next.x)
                                 | ((unsigned)(cen.y >= pm_next.y) << 1)
                                 | ((unsigned)(cen.z >= pm_next.z) << 2)
                                 | ((unsigned)(cen.w >= pm_next.w) << 3) );
        if (nm) {                                      // nm ⊆ em -> pg valid
            unsigned hm = nm & ( (unsigned)(pg.x == -1.0f)
                               | ((unsigned)(pg.y == -1.0f) << 1)
                               | ((unsigned)(pg.z == -1.0f) << 2)
                               | ((unsigned)(pg.w == -1.0f) << 3) );
            while (hm) {                               // ~<=1 iteration typically
                const int bsel = __ffs(hm) - 1; hm &= hm - 1;
                const float c = (bsel & 1) ? ((bsel & 2) ? cen.w : cen.y)
                                           : ((bsel & 2) ? cen.z : cen.x);
                const float t = 1.0f + __expf(-c);     // 1 + e^-c
                const float s = 1.0f / t;              // sigmoid
                const float w = s * s;                 // stop_grad(prob)^2
                s_w  += w;
                s_lw += w * (c + __logf(t));           // -log(1-s) = c + log(1+e^-c)
            }
        }
        pmm = pmc; pmc = pm_next; cen = c1;
    };

    if (relmax >= ZC + 1) {
        // steady-state chunk (7 of 8): no z clamp, fully unrolled,
        // plane offsets fold into LDG immediates, loads front-batched
        #pragma unroll
        for (int i = 0; i < ZC; ++i) step(i, i + 2);
    } else {
        // last chunk: clamp prefetch plane to D-1 (SAME padding in z)
        #pragma unroll
        for (int i = 0; i < ZC; ++i) {
            int rn = i + 2; if (rn > relmax) rn = relmax;
            step(i, rn);
        }
    }

    // ---- block reduction -> per-block partial (single barrier at the end)
    #pragma unroll
    for (int o = 16; o; o >>= 1) {
        s_lw += __shfl_down_sync(FULLMASK, s_lw, o);
        s_w  += __shfl_down_sync(FULLMASK, s_w,  o);
    }
    const int lane = tid & 31, w = tid >> 5;
    if (lane == 0) { sred[w] = s_lw; sred[8 + w] = s_w; }
    __syncthreads();
    if (tid == 0) {
        float a = 0.f, b = 0.f;
        #pragma unroll
        for (int i = 0; i < 8; i++) { a += sred[i]; b += sred[8 + i]; }
        g_part[gbid] = make_float2(a, b);
    }
}

// ---------------------------------------------------------------------------
// Positive branch (dedicated block). Threads 0-127: level a, 128-255: level b.
// ---------------------------------------------------------------------------
__device__ __forceinline__ void pos_impl(const float* __restrict__ La, const int* __restrict__ Ca,
                                         const int* __restrict__ coA,
                                         const float* __restrict__ Lb, const int* __restrict__ Cb,
                                         const int* __restrict__ coB,
                                         int* ssegmin, double* sdbl)
{
    const int t = threadIdx.x;
    if (t < 32) ssegmin[t] = 0x7F800000;   // +inf

    const int lvl = t >> 7, u = t & 127;
    const int b = u >> 6, m = u & 63;
    const float* L  = lvl ? Lb  : La;
    const int*   C  = lvl ? Cb  : Ca;
    const int*   CO = lvl ? coB : coA;
    const int    D  = lvl ? 64  : 128;

    const int* row = CO + (size_t)(b * 64 + m) * 4;
    int c0 = row[0], c1 = row[1], c2 = row[2], c3 = row[3];
    const bool valid = (c0 > -1);
    if (!valid) { c0 = c1 = c2 = c3 = 0; }
    const size_t idx = ((((size_t)(b * 2 + c0) * D + c1) * D + c2) * D + c3);
    const float lp = L[idx];
    const float s  = 1.0f / (1.0f + __expf(-lp));
    const float om = 1.0f - s;
    const float w1 = om * om;
    const float nll = fmaxf(-lp, 0.f) + __logf(1.f + __expf(-fabsf(lp)));
    float loss = valid ? nll * w1 : 0.f;               // -log_sigmoid(lp)*w1 (w2==1)
    float w1v  = valid ? w1 : 0.f;

    __syncthreads();                                   // ssegmin init visible
    if (valid) {
        const int tag = C[idx];
        atomicMin(&ssegmin[lvl * 16 + b * 8 + tag], __float_as_int(w1));
    }

    #pragma unroll
    for (int o = 16; o; o >>= 1) {
        loss += __shfl_down_sync(FULLMASK, loss, o);
        w1v  += __shfl_down_sync(FULLMASK, w1v,  o);
    }
    const int lane = t & 31, wi = t >> 5;
    if (lane == 0) {
        sdbl[(lvl * 2 + 0) * 4 + (wi & 3)] = (double)loss;
        sdbl[(lvl * 2 + 1) * 4 + (wi & 3)] = (double)w1v;
    }
    __syncthreads();
    if (t < 4) {
        double acc = 0.0;
        #pragma unroll
        for (int i = 0; i < 4; i++) acc += sdbl[t * 4 + i];
        g_posv[t] = acc;   // {loss0, w0, loss1, w1}
    }
    if (t < 32) g_segres[t] = ssegmin[t];
}

// ---------------------------------------------------------------------------
// Finalize (last block to finish; cross-SM reads via __ldcg).
// ---------------------------------------------------------------------------
__device__ __forceinline__ void finalize(float* __restrict__ out, double* sdbl)
{
    const int t = threadIdx.x;
    double nl0 = 0, nw0 = 0, nl1 = 0, nw1 = 0;
    for (int i = t; i < NBLK; i += 256) {
        float2 p = __ldcg(&g_part[i]);
        if (i < NBLK_A) { nl0 += (double)p.x; nw0 += (double)p.y; }
        else            { nl1 += (double)p.x; nw1 += (double)p.y; }
    }
    #pragma unroll
    for (int o = 16; o; o >>= 1) {
        nl0 += __shfl_down_sync(FULLMASK, nl0, o);
        nw0 += __shfl_down_sync(FULLMASK, nw0, o);
        nl1 += __shfl_down_sync(FULLMASK, nl1, o);
        nw1 += __shfl_down_sync(FULLMASK, nw1, o);
    }
    const int lane = t & 31, wi = t >> 5;
    if (lane == 0) {
        sdbl[0 * 8 + wi] = nl0; sdbl[1 * 8 + wi] = nw0;
        sdbl[2 * 8 + wi] = nl1; sdbl[3 * 8 + wi] = nw1;
    }
    __syncthreads();
    if (t == 0) {
        double NL0 = 0, NW0 = 0, NL1 = 0, NW1 = 0;
        #pragma unroll
        for (int i = 0; i < 8; i++) {
            NL0 += sdbl[0 * 8 + i]; NW0 += sdbl[1 * 8 + i];
            NL1 += sdbl[2 * 8 + i]; NW1 += sdbl[3 * 8 + i];
        }
        const double pl0 = __ldcg(&g_posv[0]), pw0 = __ldcg(&g_posv[1]);
        const double pl1 = __ldcg(&g_posv[2]), pw1 = __ldcg(&g_posv[3]);
        // POS_FACTOR == NEG_FACTOR == [2, 1]
        out[0] = (float)(pl0 * 2.0 + pl1);   // cls_loss_pos
        out[1] = (float)(NL0 * 2.0 + NL1);   // cls_loss_neg
        out[2] = (float)(pw0       + pw1);   // count_pos
        out[3] = (float)(NW0       + NW1);   // count_neg
        out[4] = (float)(pw0 * 2.0 + pw1);   // wsum_pos
        out[5] = (float)(NW0 * 2.0 + NW1);   // wsum_neg
    }
    if (t < 32) {
        const int bits = __ldcg(&g_segres[t]);
        out[6 + t] = (bits == 0x7F800000) ? -1.0f : __int_as_float(bits);
    }
}

// ---------------------------------------------------------------------------
__global__ __launch_bounds__(256, 4)   // 64-reg budget, no spills (R11-proven)
void fused_kernel(const float* __restrict__ La, const float* __restrict__ Pa,
                  const float* __restrict__ Lb, const float* __restrict__ Pb,
                  const int* __restrict__ Ca, const int* __restrict__ Cb,
                  const int* __restrict__ coA, const int* __restrict__ coB,
                  float* __restrict__ out)
{
    __shared__ float  sred[16];
    __shared__ double sdbl[32];
    __shared__ int    ssegmin[32];
    __shared__ bool   slast;

    const int bid = blockIdx.x;
    if (bid == NBLK)        pos_impl(La, Ca, coA, Lb, Cb, coB, ssegmin, sdbl);
    else if (bid < NBLK_A)  neg_impl<128, A_YT, A_ZT>(La, Pa, bid, bid, sred);
    else                    neg_impl<64,  B_YT, B_ZT>(Lb, Pb, bid - NBLK_A, bid, sred);

    // last-block ticket
    __threadfence();
    if (threadIdx.x == 0) {
        unsigned tk = atomicAdd(&g_done, 1u);
        slast = (tk == (unsigned)NBLK);   // NBLK+1 blocks total
    }
    __syncthreads();
    if (slast) {
        finalize(out, sdbl);
        __syncthreads();
        if (threadIdx.x == 0) g_done = 0;   // reset for next graph replay
    }
}

extern "C" void kernel_launch(void* const* d_in, const int* in_sizes, int n_in,
                              void* d_out, int out_size)
{
    (void)in_sizes; (void)n_in; (void)out_size;
    const float* logits_a = (const float*)d_in[0];
    const float* logits_b = (const float*)d_in[1];
    const float* prob_a   = (const float*)d_in[2];
    const float* prob_b   = (const float*)d_in[3];
    const int*   conn_a   = (const int*)d_in[4];
    const int*   conn_b   = (const int*)d_in[5];
    const int*   coord_a  = (const int*)d_in[6];
    const int*   coord_b  = (const int*)d_in[7];
    float* out = (float*)d_out;

    fused_kernel<<<NBLK + 1, 256>>>(logits_a, prob_a, logits_b, prob_b,
                                    conn_a, conn_b, coord_a, coord_b, out);
}

// round 17
// speedup vs baseline: 1.1766x; 1.1766x over previous
#include <cuda_runtime.h>
#include <math.h>

#define FULLMASK 0xFFFFFFFFu

// ---------------------------------------------------------------------------
// Focal_loss2 — fused focal loss, single launch, barrier-free z-march.
// R15 base (ZC=16, 577 blocks, 4 blk/SM, full unroll) with a de-branched hit
// path: the prob load is a single predicated LDG (no BSSY), the mask combine
// is unconditional ALU, and only the rare-hit while-loop remains a branch.
// Output f32[38]: [loss_pos, loss_neg, count_pos, count_neg, wsum_pos,
//                  wsum_neg, pred_prob_min[2,2,8]]
// ---------------------------------------------------------------------------

constexpr int ZC = 16;                    // z-march chunk
constexpr int A_YT = 16, A_ZT = 8;        // D=128: 8 rows/block (warp/row)
constexpr int B_YT = 4,  B_ZT = 4;        // D=64 : 16 rows/block (half-warp/row)
constexpr int NBLK_A = A_YT * A_ZT * 4;   // 512
constexpr int NBLK_B = B_YT * B_ZT * 4;   // 64
constexpr int NBLK   = NBLK_A + NBLK_B;   // 576 neg blocks (+1 pos block)

// Cross-block state (no allocation allowed -> __device__ globals).
__device__ float2   g_part[NBLK];   // neg per-block partials {sum(w*nll), sum(w)}
__device__ double   g_posv[4];      // {loss0, w0, loss1, w1}
__device__ int      g_segres[32];   // segment-min results (int-ordered floats)
__device__ unsigned g_done;         // completion ticket; reset by finalize

__device__ __forceinline__ float4 f4max(float4 a, float4 b) {
    return make_float4(fmaxf(a.x, b.x), fmaxf(a.y, b.y),
                       fmaxf(a.z, b.z), fmaxf(a.w, b.w));
}

// ---------------------------------------------------------------------------
// Negative branch, warp-autonomous: each group of LPG lanes owns one output
// row y and marches z. Out-of-range rows/planes are CLAMPED to the center
// row/plane (max unchanged — center already in window == SAME padding).
// ---------------------------------------------------------------------------
template<int D, int YT, int ZT>
__device__ __forceinline__ void neg_impl(const float* __restrict__ L,
                                         const float* __restrict__ P,
                                         int bid, int gbid, float* sred)
{
    constexpr int LPG = D / 4;        // lanes per row-group (32 for a, 16 for b)
    constexpr int GPB = 256 / LPG;    // rows per block (8 for a, 16 for b)
    constexpr int PL  = D * D;        // floats per z-plane

    const int ytile = bid % YT;
    const int zc    = (bid / YT) % ZT;
    const int ba    = bid / (YT * ZT);

    const int tid = threadIdx.x;
    const int g   = tid / LPG;        // row index in block
    const int xl  = tid % LPG;        // x lane within group
    const int x   = xl * 4;
    const int y   = ytile * GPB + g;  // 0..D-1
    const int z0  = zc * ZC;

    const size_t vol = (size_t)D * PL;
    const float* Lb = L + (size_t)ba * vol;
    const float* Pb = P + (size_t)ba * vol;

    // bases at plane z0 so unrolled-loop offsets are compile-time constants
    const float* pc0 = Lb + (size_t)z0 * PL + (size_t)y * D + x;
    const float* pm0 = (y > 0)     ? pc0 - D : pc0;       // clamped neighbors
    const float* pp0 = (y < D - 1) ? pc0 + D : pc0;
    const float* pq0 = Pb + (size_t)z0 * PL + (size_t)y * D + x;

    auto ld3 = [&](int rel, float4& r0, float4& r1, float4& r2) {
        const long long o = (long long)rel * PL;
        r1 = *reinterpret_cast<const float4*>(pc0 + o);
        r0 = *reinterpret_cast<const float4*>(pm0 + o);
        r2 = *reinterpret_cast<const float4*>(pp0 + o);
    };

    // horizontal 3-max across the 4 components + lane neighbors (via shuffle).
    auto xmax3 = [&](float4 v) -> float4 {
        float lft = __shfl_up_sync(FULLMASK, v.w, 1);
        float rgt = __shfl_down_sync(FULLMASK, v.x, 1);
        if (xl == 0)       lft = -INFINITY;   // x edge (isolates half-warp groups too)
        if (xl == LPG - 1) rgt = -INFINITY;
        float4 m;
        m.x = fmaxf(lft,  fmaxf(v.x, v.y));
        m.y = fmaxf(v.x,  fmaxf(v.y, v.z));
        m.z = fmaxf(v.y,  fmaxf(v.z, v.w));
        m.w = fmaxf(rgt,  fmaxf(v.z, v.w));
        return m;
    };

    // ---- prologue: pm(z0-1 clamped), pm(z0); plane z0+1 loads in flight
    float4 a0, a1, a2, b0, b1, b2;
    ld3(z0 > 0 ? -1 : 0, a0, a1, a2);
    float4 pmm = xmax3(f4max(a0, f4max(a1, a2)));     // pm(z0-1)
    ld3(0, a0, a1, a2);
    float4 cen = a1;                                   // raw center @ z0
    float4 pmc = xmax3(f4max(a0, f4max(a1, a2)));     // pm(z0)
    ld3(1, b0, b1, b2);                                // z0+1 <= D-1 always

    float s_lw = 0.f, s_w = 0.f;
    const int relmax = (D - 1) - z0;                   // clamp bound in rel coords

    // one z-step: consume plane z0+i+1 (in b*), prefetch plane rel rn
    auto step = [&](int i, int rn) {
        const float4 c0 = b0, c1 = b1, c2 = b2;
        ld3(rn, b0, b1, b2);                           // issue next plane's loads
        const float4 pm_next = xmax3(f4max(c0, f4max(c1, c2)));
        const float4 M = f4max(pmm, f4max(pmc, pm_next));
        const unsigned nm = (unsigned)(M.x == cen.x)
                          | ((unsigned)(M.y == cen.y) << 1)
                          | ((unsigned)(M.z == cen.z) << 2)
                          | ((unsigned)(M.w == cen.w) << 3);
        // single-instruction conditional arm -> predicated @P LDG (no BSSY,
        // no memory traffic on non-hit lanes)
        float4 pg;
        if (nm)
            pg = __ldcs(reinterpret_cast<const float4*>(pq0 + (long long)i * PL));
        // unconditional mask combine: garbage pg on non-hit lanes is
        // neutralized by nm == 0
        const unsigned hm = nm & ( (unsigned)(pg.x == -1.0f)
                                 | ((unsigned)(pg.y == -1.0f) << 1)
                                 | ((unsigned)(pg.z == -1.0f) << 2)
                                 | ((unsigned)(pg.w == -1.0f) << 3) );
        unsigned h = hm;
        while (h) {                                    // ~<=1.3 trips per warp
            const int bsel = __ffs(h) - 1; h &= h - 1;
            const float c = (bsel & 1) ? ((bsel & 2) ? cen.w : cen.y)
                                       : ((bsel & 2) ? cen.z : cen.x);
            const float t = 1.0f + __expf(-c);         // 1 + e^-c
            const float s = 1.0f / t;                  // sigmoid
            const float w = s * s;                     // stop_grad(prob)^2
            s_w  += w;
            s_lw += w * (c + __logf(t));               // -log(1-s) = c + log(1+e^-c)
        }
        pmm = pmc; pmc = pm_next; cen = c1;
    };

    if (relmax >= ZC + 1) {
        // steady-state chunk (7 of 8): no z clamp, fully unrolled,
        // plane offsets fold into LDG immediates, loads front-batched
        #pragma unroll
        for (int i = 0; i < ZC; ++i) step(i, i + 2);
    } else {
        // last chunk: clamp prefetch plane to D-1 (SAME padding in z)
        #pragma unroll
        for (int i = 0; i < ZC; ++i) {
            int rn = i + 2; if (rn > relmax) rn = relmax;
            step(i, rn);
        }
    }

    // ---- block reduction -> per-block partial (single barrier at the end)
    #pragma unroll
    for (int o = 16; o; o >>= 1) {
        s_lw += __shfl_down_sync(FULLMASK, s_lw, o);
        s_w  += __shfl_down_sync(FULLMASK, s_w,  o);
    }
    const int lane = tid & 31, w = tid >> 5;
    if (lane == 0) { sred[w] = s_lw; sred[8 + w] = s_w; }
    __syncthreads();
    if (tid == 0) {
        float a = 0.f, b = 0.f;
        #pragma unroll
        for (int i = 0; i < 8; i++) { a += sred[i]; b += sred[8 + i]; }
        g_part[gbid] = make_float2(a, b);
    }
}

// ---------------------------------------------------------------------------
// Positive branch (dedicated block). Threads 0-127: level a, 128-255: level b.
// ---------------------------------------------------------------------------
__device__ __forceinline__ void pos_impl(const float* __restrict__ La, const int* __restrict__ Ca,
                                         const int* __restrict__ coA,
                                         const float* __restrict__ Lb, const int* __restrict__ Cb,
                                         const int* __restrict__ coB,
                                         int* ssegmin, double* sdbl)
{
    const int t = threadIdx.x;
    if (t < 32) ssegmin[t] = 0x7F800000;   // +inf

    const int lvl = t >> 7, u = t & 127;
    const int b = u >> 6, m = u & 63;
    const float* L  = lvl ? Lb  : La;
    const int*   C  = lvl ? Cb  : Ca;
    const int*   CO = lvl ? coB : coA;
    const int    D  = lvl ? 64  : 128;

    const int* row = CO + (size_t)(b * 64 + m) * 4;
    int c0 = row[0], c1 = row[1], c2 = row[2], c3 = row[3];
    const bool valid = (c0 > -1);
    if (!valid) { c0 = c1 = c2 = c3 = 0; }
    const size_t idx = ((((size_t)(b * 2 + c0) * D + c1) * D + c2) * D + c3);
    const float lp = L[idx];
    const float s  = 1.0f / (1.0f + __expf(-lp));
    const float om = 1.0f - s;
    const float w1 = om * om;
    const float nll = fmaxf(-lp, 0.f) + __logf(1.f + __expf(-fabsf(lp)));
    float loss = valid ? nll * w1 : 0.f;               // -log_sigmoid(lp)*w1 (w2==1)
    float w1v  = valid ? w1 : 0.f;

    __syncthreads();                                   // ssegmin init visible
    if (valid) {
        const int tag = C[idx];
        atomicMin(&ssegmin[lvl * 16 + b * 8 + tag], __float_as_int(w1));
    }

    #pragma unroll
    for (int o = 16; o; o >>= 1) {
        loss += __shfl_down_sync(FULLMASK, loss, o);
        w1v  += __shfl_down_sync(FULLMASK, w1v,  o);
    }
    const int lane = t & 31, wi = t >> 5;
    if (lane == 0) {
        sdbl[(lvl * 2 + 0) * 4 + (wi & 3)] = (double)loss;
        sdbl[(lvl * 2 + 1) * 4 + (wi & 3)] = (double)w1v;
    }
    __syncthreads();
    if (t < 4) {
        double acc = 0.0;
        #pragma unroll
        for (int i = 0; i < 4; i++) acc += sdbl[t * 4 + i];
        g_posv[t] = acc;   // {loss0, w0, loss1, w1}
    }
    if (t < 32) g_segres[t] = ssegmin[t];
}

// ---------------------------------------------------------------------------
// Finalize (last block to finish; cross-SM reads via __ldcg).
// ---------------------------------------------------------------------------
__device__ __forceinline__ void finalize(float* __restrict__ out, double* sdbl)
{
    const int t = threadIdx.x;
    double nl0 = 0, nw0 = 0, nl1 = 0, nw1 = 0;
    for (int i = t; i < NBLK; i += 256) {
        float2 p = __ldcg(&g_part[i]);
        if (i < NBLK_A) { nl0 += (double)p.x; nw0 += (double)p.y; }
        else            { nl1 += (double)p.x; nw1 += (double)p.y; }
    }
    #pragma unroll
    for (int o = 16; o; o >>= 1) {
        nl0 += __shfl_down_sync(FULLMASK, nl0, o);
        nw0 += __shfl_down_sync(FULLMASK, nw0, o);
        nl1 += __shfl_down_sync(FULLMASK, nl1, o);
        nw1 += __shfl_down_sync(FULLMASK, nw1, o);
    }
    const int lane = t & 31, wi = t >> 5;
    if (lane == 0) {
        sdbl[0 * 8 + wi] = nl0; sdbl[1 * 8 + wi] = nw0;
        sdbl[2 * 8 + wi] = nl1; sdbl[3 * 8 + wi] = nw1;
    }
    __syncthreads();
    if (t == 0) {
        double NL0 = 0, NW0 = 0, NL1 = 0, NW1 = 0;
        #pragma unroll
        for (int i = 0; i < 8; i++) {
            NL0 += sdbl[0 * 8 + i]; NW0 += sdbl[1 * 8 + i];
            NL1 += sdbl[2 * 8 + i]; NW1 += sdbl[3 * 8 + i];
        }
        const double pl0 = __ldcg(&g_posv[0]), pw0 = __ldcg(&g_posv[1]);
        const double pl1 = __ldcg(&g_posv[2]), pw1 = __ldcg(&g_posv[3]);
        // POS_FACTOR == NEG_FACTOR == [2, 1]
        out[0] = (float)(pl0 * 2.0 + pl1);   // cls_loss_pos
        out[1] = (float)(NL0 * 2.0 + NL1);   // cls_loss_neg
        out[2] = (float)(pw0       + pw1);   // count_pos
        out[3] = (float)(NW0       + NW1);   // count_neg
        out[4] = (float)(pw0 * 2.0 + pw1);   // wsum_pos
        out[5] = (float)(NW0 * 2.0 + NW1);   // wsum_neg
    }
    if (t < 32) {
        const int bits = __ldcg(&g_segres[t]);
        out[6 + t] = (bits == 0x7F800000) ? -1.0f : __int_as_float(bits);
    }
}

// ---------------------------------------------------------------------------
__global__ __launch_bounds__(256, 4)   // 64-reg budget, no spills (R11-proven)
void fused_kernel(const float* __restrict__ La, const float* __restrict__ Pa,
                  const float* __restrict__ Lb, const float* __restrict__ Pb,
                  const int* __restrict__ Ca, const int* __restrict__ Cb,
                  const int* __restrict__ coA, const int* __restrict__ coB,
                  float* __restrict__ out)
{
    __shared__ float  sred[16];
    __shared__ double sdbl[32];
    __shared__ int    ssegmin[32];
    __shared__ bool   slast;

    const int bid = blockIdx.x;
    if (bid == NBLK)        pos_impl(La, Ca, coA, Lb, Cb, coB, ssegmin, sdbl);
    else if (bid < NBLK_A)  neg_impl<128, A_YT, A_ZT>(La, Pa, bid, bid, sred);
    else                    neg_impl<64,  B_YT, B_ZT>(Lb, Pb, bid - NBLK_A, bid, sred);

    // last-block ticket
    __threadfence();
    if (threadIdx.x == 0) {
        unsigned tk = atomicAdd(&g_done, 1u);
        slast = (tk == (unsigned)NBLK);   // NBLK+1 blocks total
    }
    __syncthreads();
    if (slast) {
        finalize(out, sdbl);
        __syncthreads();
        if (threadIdx.x == 0) g_done = 0;   // reset for next graph replay
    }
}

extern "C" void kernel_launch(void* const* d_in, const int* in_sizes, int n_in,
                              void* d_out, int out_size)
{
    (void)in_sizes; (void)n_in; (void)out_size;
    const float* logits_a = (const float*)d_in[0];
    const float* logits_b = (const float*)d_in[1];
    const float* prob_a   = (const float*)d_in[2];
    const float* prob_b   = (const float*)d_in[3];
    const int*   conn_a   = (const int*)d_in[4];
    const int*   conn_b   = (const int*)d_in[5];
    const int*   coord_a  = (const int*)d_in[6];
    const int*   coord_b  = (const int*)d_in[7];
    float* out = (float*)d_out;

    fused_kernel<<<NBLK + 1, 256>>>(logits_a, prob_a, logits_b, prob_b,
                                    conn_a, conn_b, coord_a, coord_b, out);
}